// round 5
// baseline (speedup 1.0000x reference)
#include <cuda_runtime.h>
#include <math.h>

#define NBLK 5
#define NSEG 4
#define BB   32
#define LL   128
#define NP   1024
#define EE   768
#define HH   512
#define PP   256
#define HDD  128
#define GG   2048
#define MT   4096
#define SCALE 0.08838834764831845f

// ---- scratch arena: phase-disjoint regions, 240 MB total ----
#define OFF_GIH   0L
#define OFF_MID   0L
#define OFF_H0SEQ 41943040L                 // 5*4096*2048
#define OFF_H     52428800L                 // + 5*4096*512
#define OFF_K     0L
#define OFF_V     16777216L                 // 32*1024*512
#define ARENA_FLOATS 62914560L              // 240 MB

__device__ __align__(16) float g_arena[ARENA_FLOATS];
__device__ __align__(16) float g_hbuf [2*NBLK*BB*HH];
__device__ __align__(16) float g_cbuf [NBLK*BB*HH];
__device__ __align__(16) float g_gb   [NBLK*2*GG];
__device__ __align__(16) float g_last [NBLK*BB*HH];
__device__ __align__(16) float g_blk  [NBLK*BB*HH];
__device__ __align__(16) float g_q    [NSEG*BB*HH];
__device__ __align__(16) float g_att  [NSEG*BB*HH];
__device__ __align__(16) float g_res  [NSEG*BB*HH];
__device__ int   g_anyv [NSEG*BB];
__device__ __align__(16) float g_c1   [BB*128];
__device__ __align__(16) float g_c2   [BB*16];
__device__ __align__(16) float g_c3   [BB*3];

// ---- software grid barrier (generation counter) ----
__device__ int g_bar_count;
__device__ volatile int g_bar_gen;

__device__ __forceinline__ void grid_bar(int nb) {
    __syncthreads();
    if (threadIdx.x == 0) {
        int gen = g_bar_gen;
        __threadfence();
        if (atomicAdd(&g_bar_count, 1) == nb - 1) {
            g_bar_count = 0;
            __threadfence();
            g_bar_gen = gen + 1;
        } else {
            while (g_bar_gen == gen) __nanosleep(64);
        }
    }
    __syncthreads();
}

// ---- generic tiled GEMM: C = act(A@W + bias), batched over blockIdx.z ----
template<int ACT>  // 0 none, 1 leaky relu, 2 relu
__global__ void gemm_k(const float* __restrict__ A0, long sA,
                       const float* __restrict__ W0, long sW,
                       const float* __restrict__ b0, long sB,
                       float* __restrict__ C0, long sC,
                       int M, int K, int N)
{
    const float* A = A0 + (long)blockIdx.z * sA;
    const float* W = W0 + (long)blockIdx.z * sW;
    const float* bias = b0 + (long)blockIdx.z * sB;
    float* C = C0 + (long)blockIdx.z * sC;
    int bm = blockIdx.y * 64, bn = blockIdx.x * 64, tid = threadIdx.x;

    __shared__ __align__(16) float shA[16][68];
    __shared__ __align__(16) float shW[16][64];
    int tm = (tid >> 4) * 4, tn = (tid & 15) * 4;
    float acc[4][4] = {};

    for (int k0 = 0; k0 < K; k0 += 16) {
        #pragma unroll
        for (int i = 0; i < 4; i++) {
            int e = tid + i * 256, m = e >> 4, kk = e & 15;
            int gm = bm + m;
            shA[kk][m] = (gm < M) ? A[(long)gm * K + k0 + kk] : 0.f;
        }
        #pragma unroll
        for (int i = 0; i < 4; i++) {
            int e = tid + i * 256, kk = e >> 6, n = e & 63;
            int gn = bn + n;
            shW[kk][n] = (gn < N) ? W[(long)(k0 + kk) * N + gn] : 0.f;
        }
        __syncthreads();
        #pragma unroll
        for (int kk = 0; kk < 16; kk++) {
            float4 av = *(const float4*)&shA[kk][tm];
            float4 bv = *(const float4*)&shW[kk][tn];
            float a[4] = {av.x, av.y, av.z, av.w};
            float b[4] = {bv.x, bv.y, bv.z, bv.w};
            #pragma unroll
            for (int i = 0; i < 4; i++)
                #pragma unroll
                for (int j = 0; j < 4; j++)
                    acc[i][j] += a[i] * b[j];
        }
        __syncthreads();
    }
    #pragma unroll
    for (int i = 0; i < 4; i++) {
        int m = bm + tm + i;
        if (m >= M) continue;
        #pragma unroll
        for (int j = 0; j < 4; j++) {
            int n = bn + tn + j;
            if (n >= N) continue;
            float v = acc[i][j] + bias[n];
            if (ACT == 1) v = v > 0.f ? v : 0.01f * v;
            if (ACT == 2) v = fmaxf(v, 0.f);
            C[(long)m * N + n] = v;
        }
    }
}

__global__ void gb_k(const float* __restrict__ bih, const float* __restrict__ bhh) {
    int i = blockIdx.x * 256 + threadIdx.x;
    if (i < NBLK * 2 * GG) g_gb[i] = bih[i] + bhh[i];
}

// ---- persistent per-layer LSTM: grid (64,5,2) x 128 thr, all co-resident ----
// Each block owns a (16 batch x 8 unit) tile for one text-block; iterates all
// 128 timesteps internally with a software grid barrier between steps.
__global__ void __launch_bounds__(128, 8)
lstm_layer_k(const float* __restrict__ Whh_all,
             const int* __restrict__ tlen, int layer)
{
    const int NB = 64 * 5 * 2;
    const long SHC = (long)NBLK * BB * HH;   // 81920
    int blk = blockIdx.y, h0 = blockIdx.x * 8, ms = blockIdx.z * 16;
    int tid = threadIdx.x;
    const float* W = Whh_all + (long)(blk * 2 + layer) * HH * GG;

    // zero-init h(parity 0) and c: exactly one element per thread (640*128 = 81920)
    {
        long gid = ((long)((blockIdx.z * 5 + blockIdx.y) * 64 + blockIdx.x)) * 128 + tid;
        g_hbuf[gid] = 0.f;
        g_cbuf[gid] = 0.f;
    }
    grid_bar(NB);

    __shared__ __align__(16) float shH[16][17];
    __shared__ __align__(16) float shW[16][32];
    __shared__ float sg[16][36];
    int tm = tid >> 3, tn = (tid & 7) * 4;
    int um = tid >> 3, uu = tid & 7;           // cell-update mapping
    long sidx = ((long)blk * BB + (ms + um)) * HH + h0 + uu;
    int mylen = tlen[(ms + um) * NBLK + blk];

    for (int t = 0; t < LL; t++) {
        const float* A = g_hbuf + (t & 1) * SHC + ((long)blk * BB + ms) * HH;
        float* hw = g_hbuf + ((t + 1) & 1) * SHC;
        const float* G = g_arena + OFF_GIH + ((long)blk * MT + t) * GG;

        float acc[4] = {0.f, 0.f, 0.f, 0.f};
        for (int k0 = 0; k0 < HH; k0 += 16) {
            #pragma unroll
            for (int i = 0; i < 2; i++) {
                int e = tid + i * 128, m = e >> 4, kk = e & 15;
                shH[kk][m] = __ldcg(&A[(long)m * HH + k0 + kk]);   // L1-bypass: cross-SM h
            }
            #pragma unroll
            for (int i = 0; i < 4; i++) {
                int e = tid + i * 128, kk = e >> 5, n = e & 31;
                int col = (n >> 3) * HH + h0 + (n & 7);
                shW[kk][n] = W[(long)(k0 + kk) * GG + col];
            }
            __syncthreads();
            #pragma unroll
            for (int kk = 0; kk < 16; kk++) {
                float a = shH[kk][tm];
                float4 bv = *(const float4*)&shW[kk][tn];
                acc[0] += a * bv.x; acc[1] += a * bv.y;
                acc[2] += a * bv.z; acc[3] += a * bv.w;
            }
            __syncthreads();
        }
        {
            int mg = ms + tm;
            long grow = (long)mg * LL * GG;
            #pragma unroll
            for (int j = 0; j < 4; j++) {
                int n = tn + j;
                int col = (n >> 3) * HH + h0 + (n & 7);
                sg[tm][n] = acc[j] + G[grow + col];
            }
        }
        __syncthreads();
        {
            float gi = sg[um][uu], gf = sg[um][8 + uu];
            float gg2 = sg[um][16 + uu], go = sg[um][24 + uu];
            float ii = 1.f / (1.f + expf(-gi));
            float ff = 1.f / (1.f + expf(-gf));
            float gv = tanhf(gg2);
            float oo = 1.f / (1.f + expf(-go));
            float c = ff * g_cbuf[sidx] + ii * gv;
            float h = oo * tanhf(c);
            g_cbuf[sidx] = c;
            hw[sidx] = h;
            if (layer == 0)
                g_arena[OFF_H0SEQ + ((long)blk * MT + (long)(ms + um) * LL + t) * HH + h0 + uu] = h;
            else if (t == mylen - 1)
                g_last[sidx] = h;
        }
        grid_bar(NB);
    }
}

__global__ void any_k(const int* __restrict__ mask) {
    int s = blockIdx.x, b = blockIdx.y, v = 0;
    for (int n = threadIdx.x; n < NP; n += 256)
        v |= (mask[b * NP + n] == s + 1);
    v = __syncthreads_or(v);
    if (threadIdx.x == 0) g_anyv[s * BB + b] = v;
}

// ---- attention per (head, b) for segment s; K/V live in arena ----
__global__ void attn_k(const int* __restrict__ mask, int s)
{
    int h = blockIdx.x, b = blockIdx.y, tid = threadIdx.x;
    __shared__ __align__(16) float sq[128];
    __shared__ float sc[NP];
    __shared__ float red[128];

    sq[tid] = g_q[((long)s * BB + b) * HH + h * HDD + tid];
    __syncthreads();

    const float* kb = g_arena + OFF_K + (long)b * NP * HH + h * HDD;
    const float4* sq4 = (const float4*)sq;
    #pragma unroll
    for (int j = 0; j < 8; j++) {
        int n = tid + j * 128;
        const float4* kr4 = (const float4*)(kb + (long)n * HH);
        float acc = 0.f;
        #pragma unroll
        for (int d4 = 0; d4 < 32; d4++) {
            float4 kv = kr4[d4], qv = sq4[d4];
            acc += kv.x * qv.x + kv.y * qv.y + kv.z * qv.z + kv.w * qv.w;
        }
        sc[n] = (mask[b * NP + n] == s + 1) ? acc * SCALE : -1e9f;
    }
    __syncthreads();

    float lm = -3.4e38f;
    #pragma unroll
    for (int j = 0; j < 8; j++) lm = fmaxf(lm, sc[tid + j * 128]);
    red[tid] = lm; __syncthreads();
    for (int w = 64; w > 0; w >>= 1) {
        if (tid < w) red[tid] = fmaxf(red[tid], red[tid + w]);
        __syncthreads();
    }
    float mx = red[0];
    __syncthreads();
    float ls = 0.f;
    #pragma unroll
    for (int j = 0; j < 8; j++) {
        int n = tid + j * 128;
        float e = expf(sc[n] - mx);
        sc[n] = e; ls += e;
    }
    __syncthreads();
    red[tid] = ls; __syncthreads();
    for (int w = 64; w > 0; w >>= 1) {
        if (tid < w) red[tid] += red[tid + w];
        __syncthreads();
    }
    float inv = 1.f / red[0];

    const float* vb = g_arena + OFF_V + (long)b * NP * HH + h * HDD + tid;
    float o0 = 0.f, o1 = 0.f, o2 = 0.f, o3 = 0.f;
    for (int n = 0; n < NP; n += 4) {
        o0 += sc[n]     * vb[(long)n * HH];
        o1 += sc[n + 1] * vb[(long)(n + 1) * HH];
        o2 += sc[n + 2] * vb[(long)(n + 2) * HH];
        o3 += sc[n + 3] * vb[(long)(n + 3) * HH];
    }
    g_att[((long)s * BB + b) * HH + h * HDD + tid] = (o0 + o1 + o2 + o3) * inv;
}

// ---- final assembly: tg | segs(+res where any) | class_pred | cls_feat ----
__global__ void assemble_k(float* __restrict__ out, int total)
{
    int i = blockIdx.x * 256 + threadIdx.x;
    if (i >= total) return;
    const int TG = BB * HH;
    if (i < TG) { out[i] = g_blk[i]; return; }
    if (i < 5 * TG) {
        int j = i - TG, s = j >> 14, r = j & 16383, b = r >> 9;
        float v = g_blk[(s + 1) * TG + r];
        if (g_anyv[s * BB + b]) v += g_res[s * TG + r];
        out[i] = v; return;
    }
    if (i < 5 * TG + BB * 3) { out[i] = g_c3[i - 5 * TG]; return; }
    out[i] = g_blk[i - (5 * TG + BB * 3)];
}

extern "C" void kernel_launch(void* const* d_in, const int* in_sizes, int n_in,
                              void* d_out, int out_size)
{
    (void)in_sizes; (void)n_in; (void)out_size;
    const int*   tlen = (const int*)d_in[5];
    const float* radar= (const float*)d_in[6];
    const int*   mask = (const int*)d_in[7];
    const float* W1   = (const float*)d_in[8];
    const float* b1   = (const float*)d_in[9];
    const float* W2   = (const float*)d_in[10];
    const float* b2   = (const float*)d_in[11];
    const float* Wih  = (const float*)d_in[12];
    const float* Whh  = (const float*)d_in[13];
    const float* bih  = (const float*)d_in[14];
    const float* bhh  = (const float*)d_in[15];
    const float* linW = (const float*)d_in[16];
    const float* linb = (const float*)d_in[17];
    const float* Wq   = (const float*)d_in[18];
    const float* bq   = (const float*)d_in[19];
    const float* Wk   = (const float*)d_in[20];
    const float* bk   = (const float*)d_in[21];
    const float* Wv   = (const float*)d_in[22];
    const float* bv   = (const float*)d_in[23];
    const float* Wo   = (const float*)d_in[24];
    const float* bo   = (const float*)d_in[25];
    const float* cW1  = (const float*)d_in[26];
    const float* cb1  = (const float*)d_in[27];
    const float* cW2  = (const float*)d_in[28];
    const float* cb2  = (const float*)d_in[29];
    const float* cW3  = (const float*)d_in[30];
    const float* cb3  = (const float*)d_in[31];

    float *p_arena, *p_last, *p_blk, *p_q, *p_att, *p_res, *p_c1, *p_c2, *p_c3;
    cudaGetSymbolAddress((void**)&p_arena, g_arena);
    cudaGetSymbolAddress((void**)&p_last, g_last);
    cudaGetSymbolAddress((void**)&p_blk,  g_blk);
    cudaGetSymbolAddress((void**)&p_q,    g_q);
    cudaGetSymbolAddress((void**)&p_att,  g_att);
    cudaGetSymbolAddress((void**)&p_res,  g_res);
    cudaGetSymbolAddress((void**)&p_c1,   g_c1);
    cudaGetSymbolAddress((void**)&p_c2,   g_c2);
    cudaGetSymbolAddress((void**)&p_c3,   g_c3);
    float* p_gb;
    cudaGetSymbolAddress((void**)&p_gb,   g_gb);

    float* p_mid   = p_arena + OFF_MID;
    float* p_h     = p_arena + OFF_H;
    float* p_gih   = p_arena + OFF_GIH;
    float* p_h0seq = p_arena + OFF_H0SEQ;
    float* p_kbuf  = p_arena + OFF_K;
    float* p_vbuf  = p_arena + OFF_V;

    gb_k<<<(NBLK * 2 * GG + 255) / 256, 256>>>(bih, bhh);

    // per-text-block MLP
    for (int i = 0; i < 5; i++) {
        const float* ti = (const float*)d_in[i];
        gemm_k<1><<<dim3(8, 64, 1), 256>>>(ti, 0, W1 + (long)i * EE * HH, 0,
                                           b1 + (long)i * HH, 0,
                                           p_mid + (long)i * MT * HH, 0, MT, EE, HH);
    }
    gemm_k<0><<<dim3(8, 64, NBLK), 256>>>(p_mid, (long)MT * HH, W2, (long)HH * HH,
                                          b2, HH, p_h, (long)MT * HH, MT, HH, HH);

    for (int layer = 0; layer < 2; layer++) {
        const float* X = (layer == 0) ? p_h : p_h0seq;
        gemm_k<0><<<dim3(32, 64, NBLK), 256>>>(X, (long)MT * HH,
                                               Wih + (long)layer * HH * GG, 2L * HH * GG,
                                               p_gb + (long)layer * GG, 2L * GG,
                                               p_gih, (long)MT * GG, MT, HH, GG);
        lstm_layer_k<<<dim3(64, NBLK, 2), 128>>>(Whh, tlen, layer);
    }

    gemm_k<0><<<dim3(8, 1, NBLK), 256>>>(p_last, (long)BB * HH, linW, (long)HH * HH,
                                         linb, HH, p_blk, (long)BB * HH, BB, HH, HH);

    gemm_k<0><<<dim3(8, 1, NSEG), 256>>>(p_blk + (long)BB * HH, (long)BB * HH,
                                         Wq, (long)HH * HH, bq, HH,
                                         p_q, (long)BB * HH, BB, HH, HH);
    any_k<<<dim3(NSEG, BB), 256>>>(mask);

    for (int s = 0; s < NSEG; s++) {
        gemm_k<0><<<dim3(8, 512, 1), 256>>>(radar, 0, Wk + (long)s * PP * HH, 0,
                                            bk + (long)s * HH, 0,
                                            p_kbuf, 0, BB * NP, PP, HH);
        gemm_k<0><<<dim3(8, 512, 1), 256>>>(radar, 0, Wv + (long)s * PP * HH, 0,
                                            bv + (long)s * HH, 0,
                                            p_vbuf, 0, BB * NP, PP, HH);
        attn_k<<<dim3(4, BB), 128>>>(mask, s);
    }

    gemm_k<0><<<dim3(8, 1, NSEG), 256>>>(p_att, (long)BB * HH, Wo, (long)HH * HH,
                                         bo, HH, p_res, (long)BB * HH, BB, HH, HH);

    gemm_k<2><<<dim3(2, 1, 1), 256>>>(p_blk, 0, cW1, 0, cb1, 0, p_c1, 0, BB, HH, 128);
    gemm_k<2><<<dim3(1, 1, 1), 256>>>(p_c1, 0, cW2, 0, cb2, 0, p_c2, 0, BB, 128, 16);
    gemm_k<0><<<dim3(1, 1, 1), 256>>>(p_c2, 0, cW3, 0, cb3, 0, p_c3, 0, BB, 16, 3);

    const int TOTAL = BB * HH * 6 + BB * 3;   // 98400
    assemble_k<<<(TOTAL + 255) / 256, 256>>>((float*)d_out, TOTAL);
}

// round 6
// speedup vs baseline: 1.0583x; 1.0583x over previous
#include <cuda_runtime.h>
#include <math.h>

#define NBLK 5
#define NSEG 4
#define BB   32
#define LL   128
#define NP   1024
#define EE   768
#define HH   512
#define PP   256
#define HDD  128
#define GG   2048
#define MT   4096
#define SCALE 0.08838834764831845f

// ---- scratch arena: phase-disjoint regions, 240 MB total ----
#define OFF_GIH   0L
#define OFF_MID   0L
#define OFF_H0SEQ 41943040L                 // 5*4096*2048
#define OFF_H     52428800L                 // + 5*4096*512
#define OFF_K     0L
#define OFF_V     16777216L                 // 32*1024*512
#define ARENA_FLOATS 62914560L              // 240 MB

__device__ __align__(16) float g_arena[ARENA_FLOATS];
__device__ __align__(16) float g_hbuf [2*NBLK*BB*HH];
__device__ __align__(16) float g_cbuf [NBLK*BB*HH];
__device__ __align__(16) float g_gb   [NBLK*2*GG];
__device__ __align__(16) float g_last [NBLK*BB*HH];
__device__ __align__(16) float g_blk  [NBLK*BB*HH];
__device__ __align__(16) float g_q    [NSEG*BB*HH];
__device__ __align__(16) float g_att  [NSEG*BB*HH];
__device__ __align__(16) float g_res  [NSEG*BB*HH];
__device__ int   g_anyv [NSEG*BB];
__device__ __align__(16) float g_c1   [BB*128];
__device__ __align__(16) float g_c2   [BB*16];
__device__ __align__(16) float g_c3   [BB*3];

// ---- tree grid barrier: 640 blocks = 40 leaf groups x 16 ----
__device__ int g_bar_leaf[40 * 32];   // 128B stride: distinct L2 atomic addresses
__device__ int g_bar_root;
__device__ volatile int g_bar_gen;

__device__ __forceinline__ void grid_bar_tree(int group) {
    __syncthreads();
    __threadfence();                   // every thread: publish its STG before arrive
    if (threadIdx.x == 0) {
        int gen = g_bar_gen;
        if (atomicAdd(&g_bar_leaf[group * 32], 1) == 15) {
            g_bar_leaf[group * 32] = 0;
            __threadfence();
            if (atomicAdd(&g_bar_root, 1) == 39) {
                g_bar_root = 0;
                __threadfence();
                g_bar_gen = gen + 1;
            }
        }
        while (g_bar_gen == gen) __nanosleep(32);
    }
    __syncthreads();
}

// ---- small generic GEMM (64x64 tile, 4x4 micro) for short-M launches ----
template<int ACT>  // 0 none, 1 leaky relu, 2 relu
__global__ void gemm_k(const float* __restrict__ A0, long sA,
                       const float* __restrict__ W0, long sW,
                       const float* __restrict__ b0, long sB,
                       float* __restrict__ C0, long sC,
                       int M, int K, int N)
{
    const float* A = A0 + (long)blockIdx.z * sA;
    const float* W = W0 + (long)blockIdx.z * sW;
    const float* bias = b0 + (long)blockIdx.z * sB;
    float* C = C0 + (long)blockIdx.z * sC;
    int bm = blockIdx.y * 64, bn = blockIdx.x * 64, tid = threadIdx.x;

    __shared__ __align__(16) float shA[16][68];
    __shared__ __align__(16) float shW[16][64];
    int tm = (tid >> 4) * 4, tn = (tid & 15) * 4;
    float acc[4][4] = {};

    for (int k0 = 0; k0 < K; k0 += 16) {
        #pragma unroll
        for (int i = 0; i < 4; i++) {
            int e = tid + i * 256, m = e >> 4, kk = e & 15;
            int gm = bm + m;
            shA[kk][m] = (gm < M) ? A[(long)gm * K + k0 + kk] : 0.f;
        }
        #pragma unroll
        for (int i = 0; i < 4; i++) {
            int e = tid + i * 256, kk = e >> 6, n = e & 63;
            int gn = bn + n;
            shW[kk][n] = (gn < N) ? W[(long)(k0 + kk) * N + gn] : 0.f;
        }
        __syncthreads();
        #pragma unroll
        for (int kk = 0; kk < 16; kk++) {
            float4 av = *(const float4*)&shA[kk][tm];
            float4 bv = *(const float4*)&shW[kk][tn];
            float a[4] = {av.x, av.y, av.z, av.w};
            float b[4] = {bv.x, bv.y, bv.z, bv.w};
            #pragma unroll
            for (int i = 0; i < 4; i++)
                #pragma unroll
                for (int j = 0; j < 4; j++)
                    acc[i][j] += a[i] * b[j];
        }
        __syncthreads();
    }
    #pragma unroll
    for (int i = 0; i < 4; i++) {
        int m = bm + tm + i;
        if (m >= M) continue;
        #pragma unroll
        for (int j = 0; j < 4; j++) {
            int n = bn + tn + j;
            if (n >= N) continue;
            float v = acc[i][j] + bias[n];
            if (ACT == 1) v = v > 0.f ? v : 0.01f * v;
            if (ACT == 2) v = fmaxf(v, 0.f);
            C[(long)m * N + n] = v;
        }
    }
}

// ---- big GEMM: 128x64 tile, 8x4 micro (32 FFMA per 3 LDS128) ----
// Requires M%128==0, K%16==0, N%64==0 (all big launches satisfy this).
template<int ACT>
__global__ void __launch_bounds__(256)
gemm128_k(const float* __restrict__ A0, long sA,
          const float* __restrict__ W0, long sW,
          const float* __restrict__ b0, long sB,
          float* __restrict__ C0, long sC,
          int M, int K, int N)
{
    const float* A = A0 + (long)blockIdx.z * sA;
    const float* W = W0 + (long)blockIdx.z * sW;
    const float* bias = b0 + (long)blockIdx.z * sB;
    float* C = C0 + (long)blockIdx.z * sC;
    int bm = blockIdx.y * 128, bn = blockIdx.x * 64, tid = threadIdx.x;

    __shared__ __align__(16) float shA[16][132];   // [kk][m], pad keeps f4 align
    __shared__ __align__(16) float shW[16][64];
    int ty = tid >> 4;            // m-group: rows ty*8 .. ty*8+7
    int tx = (tid & 15) * 4;      // n offset
    float acc[8][4] = {};

    for (int k0 = 0; k0 < K; k0 += 16) {
        #pragma unroll
        for (int i = 0; i < 8; i++) {
            int e = i * 256 + tid, m = e >> 4, kk = e & 15;
            shA[kk][m] = A[(long)(bm + m) * K + k0 + kk];
        }
        #pragma unroll
        for (int i = 0; i < 4; i++) {
            int e = i * 256 + tid, kk = e >> 6, n = e & 63;
            shW[kk][n] = W[(long)(k0 + kk) * N + bn + n];
        }
        __syncthreads();
        #pragma unroll
        for (int kk = 0; kk < 16; kk++) {
            float4 b4  = *(const float4*)&shW[kk][tx];
            float4 alo = *(const float4*)&shA[kk][ty * 8];
            float4 ahi = *(const float4*)&shA[kk][ty * 8 + 4];
            float a[8] = {alo.x, alo.y, alo.z, alo.w, ahi.x, ahi.y, ahi.z, ahi.w};
            float b[4] = {b4.x, b4.y, b4.z, b4.w};
            #pragma unroll
            for (int i = 0; i < 8; i++)
                #pragma unroll
                for (int j = 0; j < 4; j++)
                    acc[i][j] += a[i] * b[j];
        }
        __syncthreads();
    }
    #pragma unroll
    for (int i = 0; i < 8; i++) {
        int m = bm + ty * 8 + i;
        float4 o;
        float v0 = acc[i][0] + bias[bn + tx + 0];
        float v1 = acc[i][1] + bias[bn + tx + 1];
        float v2 = acc[i][2] + bias[bn + tx + 2];
        float v3 = acc[i][3] + bias[bn + tx + 3];
        if (ACT == 1) {
            v0 = v0 > 0.f ? v0 : 0.01f * v0; v1 = v1 > 0.f ? v1 : 0.01f * v1;
            v2 = v2 > 0.f ? v2 : 0.01f * v2; v3 = v3 > 0.f ? v3 : 0.01f * v3;
        }
        if (ACT == 2) {
            v0 = fmaxf(v0, 0.f); v1 = fmaxf(v1, 0.f);
            v2 = fmaxf(v2, 0.f); v3 = fmaxf(v3, 0.f);
        }
        o.x = v0; o.y = v1; o.z = v2; o.w = v3;
        *(float4*)&C[(long)m * N + bn + tx] = o;
    }
}

__global__ void gb_k(const float* __restrict__ bih, const float* __restrict__ bhh) {
    int i = blockIdx.x * 256 + threadIdx.x;
    if (i < NBLK * 2 * GG) g_gb[i] = bih[i] + bhh[i];
}

// ---- persistent per-layer LSTM: grid (64,5,2) x 128 thr, all co-resident ----
__global__ void __launch_bounds__(128, 8)
lstm_layer_k(const float* __restrict__ Whh_all,
             const int* __restrict__ tlen, int layer)
{
    const long SHC = (long)NBLK * BB * HH;   // 81920
    int blk = blockIdx.y, h0 = blockIdx.x * 8, ms = blockIdx.z * 16;
    int tid = threadIdx.x;
    int group = ((blockIdx.z * 5 + blockIdx.y) * 64 + blockIdx.x) >> 4;   // 0..39
    const float* W = Whh_all + (long)(blk * 2 + layer) * HH * GG;

    // zero-init h(parity 0) and c: exactly one element per thread (640*128 = 81920)
    {
        long gid = ((long)((blockIdx.z * 5 + blockIdx.y) * 64 + blockIdx.x)) * 128 + tid;
        g_hbuf[gid] = 0.f;
        g_cbuf[gid] = 0.f;
    }
    grid_bar_tree(group);

    __shared__ __align__(16) float shH[16][17];
    __shared__ __align__(16) float shW[16][32];
    __shared__ float sg[16][36];
    int tm = tid >> 3, tn = (tid & 7) * 4;
    int um = tid >> 3, uu = tid & 7;
    long sidx = ((long)blk * BB + (ms + um)) * HH + h0 + uu;
    int mylen = tlen[(ms + um) * NBLK + blk];
    long grow = (long)(ms + tm) * LL * GG;
    int gcol[4];
    #pragma unroll
    for (int j = 0; j < 4; j++) {
        int n = tn + j;
        gcol[j] = (n >> 3) * HH + h0 + (n & 7);
    }

    for (int t = 0; t < LL; t++) {
        const float* A = g_hbuf + (t & 1) * SHC + ((long)blk * BB + ms) * HH;
        float* hw = g_hbuf + ((t + 1) & 1) * SHC;
        const float* G = g_arena + OFF_GIH + ((long)blk * MT + t) * GG;

        // prefetch gih contribution early (DRAM latency hidden under GEMM)
        float gpre[4];
        #pragma unroll
        for (int j = 0; j < 4; j++) gpre[j] = __ldg(&G[grow + gcol[j]]);

        float acc[4] = {0.f, 0.f, 0.f, 0.f};
        for (int k0 = 0; k0 < HH; k0 += 16) {
            #pragma unroll
            for (int i = 0; i < 2; i++) {
                int e = tid + i * 128, m = e >> 4, kk = e & 15;
                shH[kk][m] = __ldcg(&A[(long)m * HH + k0 + kk]);
            }
            #pragma unroll
            for (int i = 0; i < 4; i++) {
                int e = tid + i * 128, kk = e >> 5, n = e & 31;
                int col = (n >> 3) * HH + h0 + (n & 7);
                shW[kk][n] = W[(long)(k0 + kk) * GG + col];
            }
            __syncthreads();
            #pragma unroll
            for (int kk = 0; kk < 16; kk++) {
                float a = shH[kk][tm];
                float4 bv = *(const float4*)&shW[kk][tn];
                acc[0] += a * bv.x; acc[1] += a * bv.y;
                acc[2] += a * bv.z; acc[3] += a * bv.w;
            }
            __syncthreads();
        }
        #pragma unroll
        for (int j = 0; j < 4; j++) sg[tm][tn + j] = acc[j] + gpre[j];
        __syncthreads();
        {
            float gi = sg[um][uu], gf = sg[um][8 + uu];
            float gg2 = sg[um][16 + uu], go = sg[um][24 + uu];
            float ii = 1.f / (1.f + expf(-gi));
            float ff = 1.f / (1.f + expf(-gf));
            float gv = tanhf(gg2);
            float oo = 1.f / (1.f + expf(-go));
            float c = ff * g_cbuf[sidx] + ii * gv;
            float h = oo * tanhf(c);
            g_cbuf[sidx] = c;
            hw[sidx] = h;
            if (layer == 0)
                g_arena[OFF_H0SEQ + ((long)blk * MT + (long)(ms + um) * LL + t) * HH + h0 + uu] = h;
            else if (t == mylen - 1)
                g_last[sidx] = h;
        }
        if (t != LL - 1) grid_bar_tree(group);
    }
}

__global__ void any_k(const int* __restrict__ mask) {
    int s = blockIdx.x, b = blockIdx.y, v = 0;
    for (int n = threadIdx.x; n < NP; n += 256)
        v |= (mask[b * NP + n] == s + 1);
    v = __syncthreads_or(v);
    if (threadIdx.x == 0) g_anyv[s * BB + b] = v;
}

// ---- attention per (head, b) for segment s; K/V live in arena ----
__global__ void attn_k(const int* __restrict__ mask, int s)
{
    int h = blockIdx.x, b = blockIdx.y, tid = threadIdx.x;
    __shared__ __align__(16) float sq[128];
    __shared__ float sc[NP];
    __shared__ float red[128];

    sq[tid] = g_q[((long)s * BB + b) * HH + h * HDD + tid];
    __syncthreads();

    const float* kb = g_arena + OFF_K + (long)b * NP * HH + h * HDD;
    const float4* sq4 = (const float4*)sq;
    #pragma unroll
    for (int j = 0; j < 8; j++) {
        int n = tid + j * 128;
        const float4* kr4 = (const float4*)(kb + (long)n * HH);
        float acc = 0.f;
        #pragma unroll
        for (int d4 = 0; d4 < 32; d4++) {
            float4 kv = kr4[d4], qv = sq4[d4];
            acc += kv.x * qv.x + kv.y * qv.y + kv.z * qv.z + kv.w * qv.w;
        }
        sc[n] = (mask[b * NP + n] == s + 1) ? acc * SCALE : -1e9f;
    }
    __syncthreads();

    float lm = -3.4e38f;
    #pragma unroll
    for (int j = 0; j < 8; j++) lm = fmaxf(lm, sc[tid + j * 128]);
    red[tid] = lm; __syncthreads();
    for (int w = 64; w > 0; w >>= 1) {
        if (tid < w) red[tid] = fmaxf(red[tid], red[tid + w]);
        __syncthreads();
    }
    float mx = red[0];
    __syncthreads();
    float ls = 0.f;
    #pragma unroll
    for (int j = 0; j < 8; j++) {
        int n = tid + j * 128;
        float e = expf(sc[n] - mx);
        sc[n] = e; ls += e;
    }
    __syncthreads();
    red[tid] = ls; __syncthreads();
    for (int w = 64; w > 0; w >>= 1) {
        if (tid < w) red[tid] += red[tid + w];
        __syncthreads();
    }
    float inv = 1.f / red[0];

    const float* vb = g_arena + OFF_V + (long)b * NP * HH + h * HDD + tid;
    float o0 = 0.f, o1 = 0.f, o2 = 0.f, o3 = 0.f;
    for (int n = 0; n < NP; n += 4) {
        o0 += sc[n]     * vb[(long)n * HH];
        o1 += sc[n + 1] * vb[(long)(n + 1) * HH];
        o2 += sc[n + 2] * vb[(long)(n + 2) * HH];
        o3 += sc[n + 3] * vb[(long)(n + 3) * HH];
    }
    g_att[((long)s * BB + b) * HH + h * HDD + tid] = (o0 + o1 + o2 + o3) * inv;
}

// ---- final assembly ----
__global__ void assemble_k(float* __restrict__ out, int total)
{
    int i = blockIdx.x * 256 + threadIdx.x;
    if (i >= total) return;
    const int TG = BB * HH;
    if (i < TG) { out[i] = g_blk[i]; return; }
    if (i < 5 * TG) {
        int j = i - TG, s = j >> 14, r = j & 16383, b = r >> 9;
        float v = g_blk[(s + 1) * TG + r];
        if (g_anyv[s * BB + b]) v += g_res[s * TG + r];
        out[i] = v; return;
    }
    if (i < 5 * TG + BB * 3) { out[i] = g_c3[i - 5 * TG]; return; }
    out[i] = g_blk[i - (5 * TG + BB * 3)];
}

extern "C" void kernel_launch(void* const* d_in, const int* in_sizes, int n_in,
                              void* d_out, int out_size)
{
    (void)in_sizes; (void)n_in; (void)out_size;
    const int*   tlen = (const int*)d_in[5];
    const float* radar= (const float*)d_in[6];
    const int*   mask = (const int*)d_in[7];
    const float* W1   = (const float*)d_in[8];
    const float* b1   = (const float*)d_in[9];
    const float* W2   = (const float*)d_in[10];
    const float* b2   = (const float*)d_in[11];
    const float* Wih  = (const float*)d_in[12];
    const float* Whh  = (const float*)d_in[13];
    const float* bih  = (const float*)d_in[14];
    const float* bhh  = (const float*)d_in[15];
    const float* linW = (const float*)d_in[16];
    const float* linb = (const float*)d_in[17];
    const float* Wq   = (const float*)d_in[18];
    const float* bq   = (const float*)d_in[19];
    const float* Wk   = (const float*)d_in[20];
    const float* bk   = (const float*)d_in[21];
    const float* Wv   = (const float*)d_in[22];
    const float* bv   = (const float*)d_in[23];
    const float* Wo   = (const float*)d_in[24];
    const float* bo   = (const float*)d_in[25];
    const float* cW1  = (const float*)d_in[26];
    const float* cb1  = (const float*)d_in[27];
    const float* cW2  = (const float*)d_in[28];
    const float* cb2  = (const float*)d_in[29];
    const float* cW3  = (const float*)d_in[30];
    const float* cb3  = (const float*)d_in[31];

    float *p_arena, *p_last, *p_blk, *p_q, *p_att, *p_res, *p_c1, *p_c2, *p_c3, *p_gb;
    cudaGetSymbolAddress((void**)&p_arena, g_arena);
    cudaGetSymbolAddress((void**)&p_last, g_last);
    cudaGetSymbolAddress((void**)&p_blk,  g_blk);
    cudaGetSymbolAddress((void**)&p_q,    g_q);
    cudaGetSymbolAddress((void**)&p_att,  g_att);
    cudaGetSymbolAddress((void**)&p_res,  g_res);
    cudaGetSymbolAddress((void**)&p_c1,   g_c1);
    cudaGetSymbolAddress((void**)&p_c2,   g_c2);
    cudaGetSymbolAddress((void**)&p_c3,   g_c3);
    cudaGetSymbolAddress((void**)&p_gb,   g_gb);

    float* p_mid   = p_arena + OFF_MID;
    float* p_h     = p_arena + OFF_H;
    float* p_gih   = p_arena + OFF_GIH;
    float* p_h0seq = p_arena + OFF_H0SEQ;
    float* p_kbuf  = p_arena + OFF_K;
    float* p_vbuf  = p_arena + OFF_V;

    gb_k<<<(NBLK * 2 * GG + 255) / 256, 256>>>(bih, bhh);

    // per-text-block MLP (big tile GEMM)
    for (int i = 0; i < 5; i++) {
        const float* ti = (const float*)d_in[i];
        gemm128_k<1><<<dim3(8, 32, 1), 256>>>(ti, 0, W1 + (long)i * EE * HH, 0,
                                              b1 + (long)i * HH, 0,
                                              p_mid + (long)i * MT * HH, 0, MT, EE, HH);
    }
    gemm128_k<0><<<dim3(8, 32, NBLK), 256>>>(p_mid, (long)MT * HH, W2, (long)HH * HH,
                                             b2, HH, p_h, (long)MT * HH, MT, HH, HH);

    for (int layer = 0; layer < 2; layer++) {
        const float* X = (layer == 0) ? p_h : p_h0seq;
        gemm128_k<0><<<dim3(32, 32, NBLK), 256>>>(X, (long)MT * HH,
                                                  Wih + (long)layer * HH * GG, 2L * HH * GG,
                                                  p_gb + (long)layer * GG, 2L * GG,
                                                  p_gih, (long)MT * GG, MT, HH, GG);
        lstm_layer_k<<<dim3(64, NBLK, 2), 128>>>(Whh, tlen, layer);
    }

    gemm_k<0><<<dim3(8, 1, NBLK), 256>>>(p_last, (long)BB * HH, linW, (long)HH * HH,
                                         linb, HH, p_blk, (long)BB * HH, BB, HH, HH);

    gemm_k<0><<<dim3(8, 1, NSEG), 256>>>(p_blk + (long)BB * HH, (long)BB * HH,
                                         Wq, (long)HH * HH, bq, HH,
                                         p_q, (long)BB * HH, BB, HH, HH);
    any_k<<<dim3(NSEG, BB), 256>>>(mask);

    for (int s = 0; s < NSEG; s++) {
        gemm128_k<0><<<dim3(8, 256, 1), 256>>>(radar, 0, Wk + (long)s * PP * HH, 0,
                                               bk + (long)s * HH, 0,
                                               p_kbuf, 0, BB * NP, PP, HH);
        gemm128_k<0><<<dim3(8, 256, 1), 256>>>(radar, 0, Wv + (long)s * PP * HH, 0,
                                               bv + (long)s * HH, 0,
                                               p_vbuf, 0, BB * NP, PP, HH);
        attn_k<<<dim3(4, BB), 128>>>(mask, s);
    }

    gemm_k<0><<<dim3(8, 1, NSEG), 256>>>(p_att, (long)BB * HH, Wo, (long)HH * HH,
                                         bo, HH, p_res, (long)BB * HH, BB, HH, HH);

    gemm_k<2><<<dim3(2, 1, 1), 256>>>(p_blk, 0, cW1, 0, cb1, 0, p_c1, 0, BB, HH, 128);
    gemm_k<2><<<dim3(1, 1, 1), 256>>>(p_c1, 0, cW2, 0, cb2, 0, p_c2, 0, BB, 128, 16);
    gemm_k<0><<<dim3(1, 1, 1), 256>>>(p_c2, 0, cW3, 0, cb3, 0, p_c3, 0, BB, 16, 3);

    const int TOTAL = BB * HH * 6 + BB * 3;   // 98400
    assemble_k<<<(TOTAL + 255) / 256, 256>>>((float*)d_out, TOTAL);
}